// round 11
// baseline (speedup 1.0000x reference)
#include <cuda_runtime.h>
#include <cuda_fp16.h>
#include <math.h>
#include <stdint.h>

// Problem constants
#define NT   4096   // B*T tokens
#define DD   1024   // model dim
#define HH   4096   // hidden dim
#define NE   8      // experts
#define TOPK 2

#define BM 128
#define BN 256
#define KC 64
#define STAGES 3

// ---------------- scratch (static device, no allocation) ----------------
__device__ int   g_cnt[NE];
__device__ int   g_tok [NE * NT];
__device__ float g_gw  [NE * NT];
__device__ int   g_hrow[NE * NT];

__device__ __half g_xf[(size_t)NT * DD];
__device__ __half g_w1f[(size_t)NE * DD * HH];
__device__ __half g_w2f[(size_t)NE * HH * DD];
__device__ __half g_hf[(size_t)NT * TOPK * HH];
__device__ float  g_y[(size_t)NT * TOPK * DD];

// ---------------- PTX helpers (plain sm_103-safe) ----------------
__device__ __forceinline__ uint32_t smem_u32(const void* p) {
    uint32_t a;
    asm("{ .reg .u64 t; cvta.to.shared.u64 t, %1; cvt.u32.u64 %0, t; }" : "=r"(a) : "l"(p));
    return a;
}
__device__ __forceinline__ void cp16(uint32_t dst, const void* src, uint32_t srcsize) {
    asm volatile("cp.async.cg.shared.global [%0], [%1], 16, %2;"
                 :: "r"(dst), "l"(src), "r"(srcsize) : "memory");
}
#define CP_COMMIT()  asm volatile("cp.async.commit_group;" ::: "memory")
#define CP_WAIT1()   asm volatile("cp.async.wait_group 1;" ::: "memory")
#define CP_WAIT0()   asm volatile("cp.async.wait_group 0;" ::: "memory")

__device__ __forceinline__ void ldsm4(uint32_t* r, uint32_t addr) {
    asm volatile("ldmatrix.sync.aligned.m8n8.x4.shared.b16 {%0,%1,%2,%3}, [%4];"
                 : "=r"(r[0]), "=r"(r[1]), "=r"(r[2]), "=r"(r[3]) : "r"(addr));
}
__device__ __forceinline__ void ldsm4t(uint32_t* r, uint32_t addr) {
    asm volatile("ldmatrix.sync.aligned.m8n8.x4.trans.shared.b16 {%0,%1,%2,%3}, [%4];"
                 : "=r"(r[0]), "=r"(r[1]), "=r"(r[2]), "=r"(r[3]) : "r"(addr));
}
__device__ __forceinline__ void mma16816(float* d, const uint32_t* a, uint32_t b0, uint32_t b1) {
    asm volatile("mma.sync.aligned.m16n8k16.row.col.f32.f16.f16.f32 "
                 "{%0,%1,%2,%3}, {%4,%5,%6,%7}, {%8,%9}, {%0,%1,%2,%3};"
                 : "+f"(d[0]), "+f"(d[1]), "+f"(d[2]), "+f"(d[3])
                 : "r"(a[0]), "r"(a[1]), "r"(a[2]), "r"(a[3]), "r"(b0), "r"(b1));
}

// ---------------- SMEM layout ----------------
// A: 128 rows x 64 fp16 (128B) + 16B pad = 144B stride -> 18432 B
// B: 64 k-rows x 256 fp16 (512B) + 16B pad = 528B stride -> 33792 B
#define AST 144
#define BST 528
#define OFF_TOK  0
#define OFF_HR   512
#define OFF_GWS  1024
#define OFF_TILE 1536
#define A_OFF 0
#define B_OFF 18432
#define BUF_SZ 52224
#define SMEM_SZ (OFF_TILE + STAGES * BUF_SZ)   // 158208

// ---------------- kernel 0: zero counters ----------------
__global__ void k_zero() { if (threadIdx.x < NE) g_cnt[threadIdx.x] = 0; }

// ---------------- gating: one warp per token ----------------
__global__ void k_gate(const float* __restrict__ x,
                       const float* __restrict__ gw,
                       const float* __restrict__ gb) {
    int warp = (blockIdx.x * blockDim.x + threadIdx.x) >> 5;
    int lane = threadIdx.x & 31;
    if (warp >= NT) return;
    const float* xr = x + (size_t)warp * DD;
    float acc[NE];
#pragma unroll
    for (int e = 0; e < NE; e++) acc[e] = 0.0f;
    for (int d = lane; d < DD; d += 32) {
        float xv = xr[d];
#pragma unroll
        for (int e = 0; e < NE; e++) acc[e] += xv * gw[d * NE + e];
    }
#pragma unroll
    for (int e = 0; e < NE; e++) {
#pragma unroll
        for (int o = 16; o > 0; o >>= 1)
            acc[e] += __shfl_xor_sync(0xffffffffu, acc[e], o);
    }
    if (lane == 0) {
        float z[NE]; float m = -1e30f;
#pragma unroll
        for (int e = 0; e < NE; e++) { z[e] = acc[e] + gb[e]; m = fmaxf(m, z[e]); }
        float s = 0.0f;
#pragma unroll
        for (int e = 0; e < NE; e++) { z[e] = expf(z[e] - m); s += z[e]; }
        int i1 = 0;
#pragma unroll
        for (int e = 1; e < NE; e++) if (z[e] > z[i1]) i1 = e;
        int i2 = (i1 == 0) ? 1 : 0;
#pragma unroll
        for (int e = 0; e < NE; e++) if (e != i1 && z[e] > z[i2]) i2 = e;
        float inv = 1.0f / s;
        int es[2] = { i1, i2 };
#pragma unroll
        for (int k = 0; k < TOPK; k++) {
            int e = es[k];
            int slot = atomicAdd(&g_cnt[e], 1);
            g_tok [e * NT + slot] = warp;
            g_gw  [e * NT + slot] = z[e] * inv;
            g_hrow[e * NT + slot] = warp * TOPK + k;
        }
    }
}

// ---------------- fp32 -> fp16 preconvert ----------------
__global__ void k_conv(const float* __restrict__ src, __half* __restrict__ dst, int n4) {
    int i = blockIdx.x * blockDim.x + threadIdx.x;
    if (i >= n4) return;
    float4 v = ((const float4*)src)[i];
    __half2 a = __floats2half2_rn(v.x, v.y);
    __half2 b = __floats2half2_rn(v.z, v.w);
    ((uint2*)dst)[i] = make_uint2(*(uint32_t*)&a, *(uint32_t*)&b);
}

// ---------------- tile fill (cp.async) ----------------
__device__ __forceinline__ void fill_tiles(uint32_t tb, int tid,
                                           const __half* __restrict__ A, int a_ld,
                                           const int* rows,
                                           const __half* __restrict__ B, int b_ld,
                                           int n0, int k0) {
    // A: 128 rows x 64 fp16 = 8 x 16B chunks/row -> 1024 chunks, 4/thread
#pragma unroll
    for (int i = 0; i < 4; i++) {
        int id = tid + i * 256;
        int r = id >> 3, c = id & 7;
        int t = rows[r];
        size_t off = (size_t)(t < 0 ? 0 : t) * a_ld + k0 + c * 8;
        cp16(tb + A_OFF + r * AST + c * 16, A + off, (t < 0) ? 0u : 16u);
    }
    // B: 64 k-rows x 256 fp16 = 32 x 16B chunks/row -> 2048 chunks, 8/thread
#pragma unroll
    for (int i = 0; i < 8; i++) {
        int id = tid + i * 256;
        int r = id >> 5, c = id & 31;
        size_t off = (size_t)(k0 + r) * b_ld + n0 + c * 8;
        cp16(tb + B_OFF + r * BST + c * 16, B + off, 16u);
    }
}

// ---------------- fragment load for one k16 step ----------------
__device__ __forceinline__ void ld_frags(uint32_t tb, int lane, int wm, int wn, int kk,
                                         uint32_t a[4][4], uint32_t b[4][4]) {
    int t  = lane >> 3;
    int lr = lane & 7;
#pragma unroll
    for (int mt = 0; mt < 4; mt++) {
        uint32_t addr = tb + A_OFF + (uint32_t)(wm + mt * 16 + (t & 1) * 8 + lr) * AST
                      + (uint32_t)(kk * 16 + (t >> 1) * 8) * 2;
        ldsm4(a[mt], addr);
    }
#pragma unroll
    for (int j = 0; j < 4; j++) {
        uint32_t addr = tb + B_OFF + (uint32_t)(kk * 16 + (t & 1) * 8 + lr) * BST
                      + (uint32_t)(wn + j * 16 + (t >> 1) * 8) * 2;
        ldsm4t(b[j], addr);
    }
}

__device__ __forceinline__ void mma_all(uint32_t a[4][4], uint32_t b[4][4],
                                        float acc[4][8][4]) {
#pragma unroll
    for (int j = 0; j < 4; j++) {
#pragma unroll
        for (int mt = 0; mt < 4; mt++) {
            mma16816(acc[mt][j * 2 + 0], a[mt], b[j][0], b[j][1]);
            mma16816(acc[mt][j * 2 + 1], a[mt], b[j][2], b[j][3]);
        }
    }
}

// pipelined mainloop shared by both FC kernels (NCH > STAGES-1)
__device__ __forceinline__ void gemm_mainloop(uint32_t sb, int tid, int lane, int wm, int wn,
                                              const __half* __restrict__ A, int a_ld,
                                              const int* rows,
                                              const __half* __restrict__ B, int b_ld,
                                              int n0, int NCH, float acc[4][8][4]) {
    // prologue: fill stages 0,1
#pragma unroll
    for (int s = 0; s < STAGES - 1; s++) {
        fill_tiles(sb + OFF_TILE + s * BUF_SZ, tid, A, a_ld, rows, B, b_ld, n0, s * KC);
        CP_COMMIT();
    }
    int stage = 0;
    uint32_t af[2][4][4], bf[2][4][4];
    for (int c = 0; c < NCH; c++) {
        if (c + 1 < NCH) CP_WAIT1(); else CP_WAIT0();
        __syncthreads();   // stage c visible; all warps done with stage being refilled
        if (c + STAGES - 1 < NCH) {
            int fs = stage + STAGES - 1; if (fs >= STAGES) fs -= STAGES;
            fill_tiles(sb + OFF_TILE + fs * BUF_SZ, tid, A, a_ld, rows, B, b_ld, n0,
                       (c + STAGES - 1) * KC);
            CP_COMMIT();
        }
        uint32_t tb = sb + OFF_TILE + stage * BUF_SZ;
        ld_frags(tb, lane, wm, wn, 0, af[0], bf[0]);
#pragma unroll
        for (int kk = 0; kk < KC / 16; kk++) {
            if (kk + 1 < KC / 16)
                ld_frags(tb, lane, wm, wn, kk + 1, af[(kk + 1) & 1], bf[(kk + 1) & 1]);
            mma_all(af[kk & 1], bf[kk & 1], acc);
        }
        stage++; if (stage >= STAGES) stage = 0;
    }
}

// ---------------- FC1: h[hrow] = relu(x[tok] @ w1[e] + b1[e]) -> fp16 ----------------
__global__ void __launch_bounds__(256, 1)
k_fc1(const float* __restrict__ b1) {
    int e = blockIdx.z;
    int cnt = g_cnt[e];
    int m0 = blockIdx.y * BM;
    if (m0 >= cnt) return;
    int n0 = blockIdx.x * BN;

    extern __shared__ char smem[];
    uint32_t sb = smem_u32(smem);
    int tid = threadIdx.x, wid = tid >> 5, lane = tid & 31;
    int* toks  = (int*)(smem + OFF_TOK);
    int* hrows = (int*)(smem + OFF_HR);
    if (tid < BM) {
        int s = m0 + tid;
        toks [tid] = (s < cnt) ? g_tok [e * NT + s] : -1;
        hrows[tid] = (s < cnt) ? g_hrow[e * NT + s] : -1;
    }
    __syncthreads();

    const __half* W = g_w1f + (size_t)e * DD * HH;

    float acc[4][8][4];
#pragma unroll
    for (int a = 0; a < 4; a++)
#pragma unroll
        for (int b = 0; b < 8; b++)
#pragma unroll
            for (int c = 0; c < 4; c++) acc[a][b][c] = 0.0f;

    int wm = (wid & 1) * 64, wn = (wid >> 1) * 64;

    gemm_mainloop(sb, tid, lane, wm, wn, g_xf, DD, toks, W, HH, n0, DD / KC, acc);

    // epilogue: bias + relu -> fp16 h
    const float* bb = b1 + (size_t)e * HH + n0;
#pragma unroll
    for (int mt = 0; mt < 4; mt++) {
#pragma unroll
        for (int nt = 0; nt < 8; nt++) {
            int col = wn + nt * 8 + (lane & 3) * 2;
            float bv0 = bb[col], bv1 = bb[col + 1];
#pragma unroll
            for (int half = 0; half < 2; half++) {
                int li = wm + mt * 16 + (lane >> 2) + half * 8;
                int hr = hrows[li];
                if (hr < 0) continue;
                float h0 = fmaxf(acc[mt][nt][half * 2 + 0] + bv0, 0.0f);
                float h1 = fmaxf(acc[mt][nt][half * 2 + 1] + bv1, 0.0f);
                __half2 hp = __floats2half2_rn(h0, h1);
                *(uint32_t*)(g_hf + (size_t)hr * HH + n0 + col) = *(uint32_t*)&hp;
            }
        }
    }
}

// ---------------- FC2: y[hrow] = gate * (h[hrow] @ w2[e] + b2[e]) ----------------
__global__ void __launch_bounds__(256, 1)
k_fc2(const float* __restrict__ b2) {
    int e = blockIdx.z;
    int cnt = g_cnt[e];
    int m0 = blockIdx.y * BM;
    if (m0 >= cnt) return;
    int n0 = blockIdx.x * BN;

    extern __shared__ char smem[];
    uint32_t sb = smem_u32(smem);
    int tid = threadIdx.x, wid = tid >> 5, lane = tid & 31;
    int*   hrows = (int*)(smem + OFF_HR);
    float* gws   = (float*)(smem + OFF_GWS);
    if (tid < BM) {
        int s = m0 + tid;
        hrows[tid] = (s < cnt) ? g_hrow[e * NT + s] : -1;
        gws  [tid] = (s < cnt) ? g_gw  [e * NT + s] : 0.0f;
    }
    __syncthreads();

    const __half* W = g_w2f + (size_t)e * HH * DD;

    float acc[4][8][4];
#pragma unroll
    for (int a = 0; a < 4; a++)
#pragma unroll
        for (int b = 0; b < 8; b++)
#pragma unroll
            for (int c = 0; c < 4; c++) acc[a][b][c] = 0.0f;

    int wm = (wid & 1) * 64, wn = (wid >> 1) * 64;

    gemm_mainloop(sb, tid, lane, wm, wn, g_hf, HH, hrows, W, DD, n0, HH / KC, acc);

    const float* bb = b2 + (size_t)e * DD + n0;
#pragma unroll
    for (int mt = 0; mt < 4; mt++) {
#pragma unroll
        for (int nt = 0; nt < 8; nt++) {
            int col = wn + nt * 8 + (lane & 3) * 2;
            float bv0 = bb[col], bv1 = bb[col + 1];
#pragma unroll
            for (int half = 0; half < 2; half++) {
                int li = wm + mt * 16 + (lane >> 2) + half * 8;
                int hr = hrows[li];
                if (hr < 0) continue;
                float g = gws[li];
                float2 o;
                o.x = g * (acc[mt][nt][half * 2 + 0] + bv0);
                o.y = g * (acc[mt][nt][half * 2 + 1] + bv1);
                *(float2*)(g_y + (size_t)hr * DD + n0 + col) = o;
            }
        }
    }
}

// ---------------- combine: out[t] = y[2t] + y[2t+1] ----------------
__global__ void k_combine(float* __restrict__ out) {
    int i = blockIdx.x * blockDim.x + threadIdx.x;
    if (i >= NT * DD / 4) return;
    int t  = i >> 8;
    int d4 = i & 255;
    const float4* y4 = (const float4*)g_y;
    float4 a = y4[(size_t)(2 * t) * 256 + d4];
    float4 b = y4[(size_t)(2 * t + 1) * 256 + d4];
    float4 o; o.x = a.x + b.x; o.y = a.y + b.y; o.z = a.z + b.z; o.w = a.w + b.w;
    ((float4*)out)[i] = o;
}

// ---------------- launch ----------------
extern "C" void kernel_launch(void* const* d_in, const int* in_sizes, int n_in,
                              void* d_out, int out_size) {
    const float* x  = (const float*)d_in[0];
    const float* gw = (const float*)d_in[1];
    const float* gb = (const float*)d_in[2];
    const float* w1 = (const float*)d_in[3];
    const float* b1 = (const float*)d_in[4];
    const float* w2 = (const float*)d_in[5];
    const float* b2 = (const float*)d_in[6];
    float* out = (float*)d_out;

    cudaFuncSetAttribute(k_fc1, cudaFuncAttributeMaxDynamicSharedMemorySize, SMEM_SZ);
    cudaFuncSetAttribute(k_fc2, cudaFuncAttributeMaxDynamicSharedMemorySize, SMEM_SZ);

    k_zero<<<1, 32>>>();
    k_gate<<<NT / 4, 128>>>(x, gw, gb);

    __half *xf, *w1f, *w2f;
    cudaGetSymbolAddress((void**)&xf,  g_xf);
    cudaGetSymbolAddress((void**)&w1f, g_w1f);
    cudaGetSymbolAddress((void**)&w2f, g_w2f);

    int nx = NT * DD / 4;
    int nw = NE * DD * HH / 4;
    k_conv<<<(nx + 255) / 256, 256>>>(x,  xf,  nx);
    k_conv<<<(nw + 255) / 256, 256>>>(w1, w1f, nw);
    k_conv<<<(nw + 255) / 256, 256>>>(w2, w2f, nw);

    dim3 g1(HH / BN, NT / BM, NE);   // 16 x 32 x 8
    k_fc1<<<g1, 256, SMEM_SZ>>>(b1);

    dim3 g2(DD / BN, NT / BM, NE);   // 4 x 32 x 8
    k_fc2<<<g2, 256, SMEM_SZ>>>(b2);

    k_combine<<<(NT * DD / 4 + 255) / 256, 256>>>(out);
}

// round 12
// speedup vs baseline: 1.0180x; 1.0180x over previous
#include <cuda_runtime.h>
#include <cuda_fp16.h>
#include <math.h>
#include <stdint.h>

// Problem constants
#define NT   4096   // B*T tokens
#define DD   1024   // model dim
#define HH   4096   // hidden dim
#define NE   8      // experts
#define TOPK 2

#define BM 128
#define BN 128
#define KC 32
#define STAGES 4

// FC2 tile
#define BM2 64

// ---------------- scratch (static device, no allocation) ----------------
__device__ int   g_cnt[NE];
__device__ int   g_tok [NE * NT];
__device__ float g_gw  [NE * NT];
__device__ int   g_hrow[NE * NT];

__device__ __half g_xf[(size_t)NT * DD];
__device__ __half g_w1f[(size_t)NE * DD * HH];
__device__ __half g_w2f[(size_t)NE * HH * DD];
__device__ __half g_hf[(size_t)NT * TOPK * HH];
__device__ float  g_y[(size_t)NT * TOPK * DD];

// ---------------- PTX helpers (plain sm_103-safe) ----------------
__device__ __forceinline__ uint32_t smem_u32(const void* p) {
    uint32_t a;
    asm("{ .reg .u64 t; cvta.to.shared.u64 t, %1; cvt.u32.u64 %0, t; }" : "=r"(a) : "l"(p));
    return a;
}
__device__ __forceinline__ void cp16(uint32_t dst, const void* src, uint32_t srcsize) {
    asm volatile("cp.async.cg.shared.global [%0], [%1], 16, %2;"
                 :: "r"(dst), "l"(src), "r"(srcsize) : "memory");
}
#define CP_COMMIT()  asm volatile("cp.async.commit_group;" ::: "memory")
#define CP_WAIT1()   asm volatile("cp.async.wait_group 1;" ::: "memory")
#define CP_WAIT0()   asm volatile("cp.async.wait_group 0;" ::: "memory")

__device__ __forceinline__ void ldsm4(uint32_t* r, uint32_t addr) {
    asm volatile("ldmatrix.sync.aligned.m8n8.x4.shared.b16 {%0,%1,%2,%3}, [%4];"
                 : "=r"(r[0]), "=r"(r[1]), "=r"(r[2]), "=r"(r[3]) : "r"(addr));
}
__device__ __forceinline__ void ldsm4t(uint32_t* r, uint32_t addr) {
    asm volatile("ldmatrix.sync.aligned.m8n8.x4.trans.shared.b16 {%0,%1,%2,%3}, [%4];"
                 : "=r"(r[0]), "=r"(r[1]), "=r"(r[2]), "=r"(r[3]) : "r"(addr));
}
__device__ __forceinline__ void mma16816(float* d, const uint32_t* a, uint32_t b0, uint32_t b1) {
    asm volatile("mma.sync.aligned.m16n8k16.row.col.f32.f16.f16.f32 "
                 "{%0,%1,%2,%3}, {%4,%5,%6,%7}, {%8,%9}, {%0,%1,%2,%3};"
                 : "+f"(d[0]), "+f"(d[1]), "+f"(d[2]), "+f"(d[3])
                 : "r"(a[0]), "r"(a[1]), "r"(a[2]), "r"(a[3]), "r"(b0), "r"(b1));
}

// ---------------- SMEM layout ----------------
// A: rows x 32 fp16 (64B) + 16B pad = 80B stride
// B: 32 k-rows x 128 fp16 (256B) + 16B pad = 272B stride -> 8704 B
#define AST 80
#define BST 272
#define OFF_TOK  0
#define OFF_HR   512
#define OFF_GWS  1024
#define OFF_TILE 1536
#define A_OFF 0
// FC1 buffers
#define B_OFF  (BM * AST)                 // 10240
#define BUF_SZ (B_OFF + 32 * BST)         // 18944
#define SMEM_SZ (OFF_TILE + STAGES * BUF_SZ)   // 77312
// FC2 buffers
#define B_OFF2  (BM2 * AST)               // 5120
#define BUF_SZ2 (B_OFF2 + 32 * BST)       // 13824
#define SMEM_SZ2 (OFF_TILE + STAGES * BUF_SZ2) // 56832

// ---------------- fused prepass: gate + 3 fp32->fp16 conversions ----------------
#define NB_GATE  (NT / 8)                   // 512 blocks, 8 warps each
#define NB_CX    (NT * DD / 4 / 256)        // 4096
#define NB_CW    (NE * DD * HH / 4 / 256)   // 32768
#define NB_TOTAL (NB_GATE + NB_CX + 2 * NB_CW)

__device__ __forceinline__ void conv4(const float* __restrict__ src,
                                      __half* __restrict__ dst, int i) {
    float4 v = ((const float4*)src)[i];
    __half2 a = __floats2half2_rn(v.x, v.y);
    __half2 b = __floats2half2_rn(v.z, v.w);
    ((uint2*)dst)[i] = make_uint2(*(uint32_t*)&a, *(uint32_t*)&b);
}

__global__ void k_prepass(const float* __restrict__ x,
                          const float* __restrict__ gw,
                          const float* __restrict__ gb,
                          const float* __restrict__ w1,
                          const float* __restrict__ w2) {
    int b = blockIdx.x;
    int tid = threadIdx.x;
    if (b < NB_GATE) {
        // ---- gating: one warp per token ----
        int lane = tid & 31;
        int tok = b * 8 + (tid >> 5);
        const float* xr = x + (size_t)tok * DD;
        float acc[NE];
#pragma unroll
        for (int e = 0; e < NE; e++) acc[e] = 0.0f;
        for (int d = lane; d < DD; d += 32) {
            float xv = xr[d];
#pragma unroll
            for (int e = 0; e < NE; e++) acc[e] += xv * gw[d * NE + e];
        }
#pragma unroll
        for (int e = 0; e < NE; e++) {
#pragma unroll
            for (int o = 16; o > 0; o >>= 1)
                acc[e] += __shfl_xor_sync(0xffffffffu, acc[e], o);
        }
        if (lane == 0) {
            float z[NE]; float m = -1e30f;
#pragma unroll
            for (int e = 0; e < NE; e++) { z[e] = acc[e] + gb[e]; m = fmaxf(m, z[e]); }
            float s = 0.0f;
#pragma unroll
            for (int e = 0; e < NE; e++) { z[e] = expf(z[e] - m); s += z[e]; }
            int i1 = 0;
#pragma unroll
            for (int e = 1; e < NE; e++) if (z[e] > z[i1]) i1 = e;
            int i2 = (i1 == 0) ? 1 : 0;
#pragma unroll
            for (int e = 0; e < NE; e++) if (e != i1 && z[e] > z[i2]) i2 = e;
            float inv = 1.0f / s;
            int es[2] = { i1, i2 };
#pragma unroll
            for (int k = 0; k < TOPK; k++) {
                int e = es[k];
                int slot = atomicAdd(&g_cnt[e], 1);
                g_tok [e * NT + slot] = tok;
                g_gw  [e * NT + slot] = z[e] * inv;
                g_hrow[e * NT + slot] = tok * TOPK + k;
            }
        }
    } else if (b < NB_GATE + NB_CX) {
        conv4(x, g_xf, (b - NB_GATE) * 256 + tid);
    } else if (b < NB_GATE + NB_CX + NB_CW) {
        conv4(w1, g_w1f, (b - NB_GATE - NB_CX) * 256 + tid);
    } else {
        conv4(w2, g_w2f, (b - NB_GATE - NB_CX - NB_CW) * 256 + tid);
    }
}

// ---------------- tile fill (cp.async) ----------------
__device__ __forceinline__ void fill_tiles(uint32_t tb, int tid,
                                           const __half* __restrict__ A, int a_ld,
                                           const int* rows,
                                           const __half* __restrict__ B, int b_ld,
                                           int n0, int k0) {
    // A: 128 rows x 32 fp16 = 4 x 16B chunks/row -> 512 chunks
#pragma unroll
    for (int i = 0; i < 2; i++) {
        int id = tid + i * 256;
        int r = id >> 2, c = id & 3;
        int t = rows[r];
        size_t off = (size_t)(t < 0 ? 0 : t) * a_ld + k0 + c * 8;
        cp16(tb + A_OFF + r * AST + c * 16, A + off, (t < 0) ? 0u : 16u);
    }
    // B: 32 k-rows x 128 fp16 = 16 x 16B chunks/row -> 512 chunks
#pragma unroll
    for (int i = 0; i < 2; i++) {
        int id = tid + i * 256;
        int r = id >> 4, c = id & 15;
        size_t off = (size_t)(k0 + r) * b_ld + n0 + c * 8;
        cp16(tb + B_OFF + r * BST + c * 16, B + off, 16u);
    }
}

// FC2: A 64 rows (1 chunk/thread), B same
__device__ __forceinline__ void fill_tiles2(uint32_t tb, int tid,
                                            const __half* __restrict__ A, int a_ld,
                                            const int* rows,
                                            const __half* __restrict__ B, int b_ld,
                                            int n0, int k0) {
    {
        int r = tid >> 2, c = tid & 3;
        int t = rows[r];
        size_t off = (size_t)(t < 0 ? 0 : t) * a_ld + k0 + c * 8;
        cp16(tb + A_OFF + r * AST + c * 16, A + off, (t < 0) ? 0u : 16u);
    }
#pragma unroll
    for (int i = 0; i < 2; i++) {
        int id = tid + i * 256;
        int r = id >> 4, c = id & 15;
        size_t off = (size_t)(k0 + r) * b_ld + n0 + c * 8;
        cp16(tb + B_OFF2 + r * BST + c * 16, B + off, 16u);
    }
}

// ---------------- mma mainloops ----------------
// FC1 warp tile 64x32: acc[4][4][4]
__device__ __forceinline__ void compute_chunk(uint32_t tb, int lane, int wm, int wn,
                                              float acc[4][4][4]) {
    int t  = lane >> 3;
    int lr = lane & 7;
#pragma unroll
    for (int k16 = 0; k16 < KC; k16 += 16) {
        uint32_t a[4][4];
#pragma unroll
        for (int mt = 0; mt < 4; mt++) {
            uint32_t addr = tb + A_OFF + (uint32_t)(wm + mt * 16 + (t & 1) * 8 + lr) * AST
                          + (uint32_t)(k16 + (t >> 1) * 8) * 2;
            ldsm4(a[mt], addr);
        }
#pragma unroll
        for (int j = 0; j < 2; j++) {
            uint32_t b[4];
            uint32_t addr = tb + B_OFF + (uint32_t)(k16 + (t & 1) * 8 + lr) * BST
                          + (uint32_t)(wn + j * 16 + (t >> 1) * 8) * 2;
            ldsm4t(b, addr);
#pragma unroll
            for (int mt = 0; mt < 4; mt++) {
                mma16816(acc[mt][j * 2 + 0], a[mt], b[0], b[1]);
                mma16816(acc[mt][j * 2 + 1], a[mt], b[2], b[3]);
            }
        }
    }
}

// FC2 warp tile 32x32: acc[2][4][4]
__device__ __forceinline__ void compute_chunk2(uint32_t tb, int lane, int wm, int wn,
                                               float acc[2][4][4]) {
    int t  = lane >> 3;
    int lr = lane & 7;
#pragma unroll
    for (int k16 = 0; k16 < KC; k16 += 16) {
        uint32_t a[2][4];
#pragma unroll
        for (int mt = 0; mt < 2; mt++) {
            uint32_t addr = tb + A_OFF + (uint32_t)(wm + mt * 16 + (t & 1) * 8 + lr) * AST
                          + (uint32_t)(k16 + (t >> 1) * 8) * 2;
            ldsm4(a[mt], addr);
        }
#pragma unroll
        for (int j = 0; j < 2; j++) {
            uint32_t b[4];
            uint32_t addr = tb + B_OFF2 + (uint32_t)(k16 + (t & 1) * 8 + lr) * BST
                          + (uint32_t)(wn + j * 16 + (t >> 1) * 8) * 2;
            ldsm4t(b, addr);
#pragma unroll
            for (int mt = 0; mt < 2; mt++) {
                mma16816(acc[mt][j * 2 + 0], a[mt], b[0], b[1]);
                mma16816(acc[mt][j * 2 + 1], a[mt], b[2], b[3]);
            }
        }
    }
}

// ---------------- FC1: h[hrow] = relu(x[tok] @ w1[e] + b1[e]) -> fp16 ----------------
__global__ void __launch_bounds__(256, 2)
k_fc1(const float* __restrict__ b1) {
    int e = blockIdx.z;
    int cnt = g_cnt[e];
    int m0 = blockIdx.y * BM;
    if (m0 >= cnt) return;
    int n0 = blockIdx.x * BN;

    extern __shared__ char smem[];
    uint32_t sb = smem_u32(smem);
    int tid = threadIdx.x, wid = tid >> 5, lane = tid & 31;
    int* toks  = (int*)(smem + OFF_TOK);
    int* hrows = (int*)(smem + OFF_HR);
    if (tid < BM) {
        int s = m0 + tid;
        toks [tid] = (s < cnt) ? g_tok [e * NT + s] : -1;
        hrows[tid] = (s < cnt) ? g_hrow[e * NT + s] : -1;
    }
    __syncthreads();

    const __half* W = g_w1f + (size_t)e * DD * HH;

    float acc[4][4][4];
#pragma unroll
    for (int a = 0; a < 4; a++)
#pragma unroll
        for (int b = 0; b < 4; b++)
#pragma unroll
            for (int c = 0; c < 4; c++) acc[a][b][c] = 0.0f;

    int wm = (wid >> 2) * 64, wn = (wid & 3) * 32;
    const int NCH = DD / KC;   // 32

#pragma unroll
    for (int s = 0; s < STAGES - 1; s++) {
        fill_tiles(sb + OFF_TILE + s * BUF_SZ, tid, g_xf, DD, toks, W, HH, n0, s * KC);
        CP_COMMIT();
    }
    int stage = 0;
    for (int c = 0; c < NCH; c++) {
        if (c + 1 < NCH) CP_WAIT1(); else CP_WAIT0();
        __syncthreads();
        if (c + STAGES - 1 < NCH) {
            int fs = stage + STAGES - 1; if (fs >= STAGES) fs -= STAGES;
            fill_tiles(sb + OFF_TILE + fs * BUF_SZ, tid, g_xf, DD, toks, W, HH, n0,
                       (c + STAGES - 1) * KC);
            CP_COMMIT();
        }
        compute_chunk(sb + OFF_TILE + stage * BUF_SZ, lane, wm, wn, acc);
        stage++; if (stage >= STAGES) stage = 0;
    }

    // epilogue: bias + relu -> fp16 h
    const float* bb = b1 + (size_t)e * HH + n0;
#pragma unroll
    for (int mt = 0; mt < 4; mt++) {
#pragma unroll
        for (int nt = 0; nt < 4; nt++) {
            int col = wn + nt * 8 + (lane & 3) * 2;
            float bv0 = bb[col], bv1 = bb[col + 1];
#pragma unroll
            for (int half = 0; half < 2; half++) {
                int li = wm + mt * 16 + (lane >> 2) + half * 8;
                int hr = hrows[li];
                if (hr < 0) continue;
                float h0 = fmaxf(acc[mt][nt][half * 2 + 0] + bv0, 0.0f);
                float h1 = fmaxf(acc[mt][nt][half * 2 + 1] + bv1, 0.0f);
                __half2 hp = __floats2half2_rn(h0, h1);
                *(uint32_t*)(g_hf + (size_t)hr * HH + n0 + col) = *(uint32_t*)&hp;
            }
        }
    }
}

// ---------------- FC2: y[hrow] = gate * (h[hrow] @ w2[e] + b2[e]), BM2=64 ----------------
__global__ void __launch_bounds__(256, 2)
k_fc2(const float* __restrict__ b2) {
    int e = blockIdx.z;
    int cnt = g_cnt[e];
    int m0 = blockIdx.y * BM2;
    if (m0 >= cnt) return;
    int n0 = blockIdx.x * BN;

    extern __shared__ char smem[];
    uint32_t sb = smem_u32(smem);
    int tid = threadIdx.x, wid = tid >> 5, lane = tid & 31;
    int*   hrows = (int*)(smem + OFF_HR);
    float* gws   = (float*)(smem + OFF_GWS);
    if (tid < BM2) {
        int s = m0 + tid;
        hrows[tid] = (s < cnt) ? g_hrow[e * NT + s] : -1;
        gws  [tid] = (s < cnt) ? g_gw  [e * NT + s] : 0.0f;
    }
    __syncthreads();

    const __half* W = g_w2f + (size_t)e * HH * DD;

    float acc[2][4][4];
#pragma unroll
    for (int a = 0; a < 2; a++)
#pragma unroll
        for (int b = 0; b < 4; b++)
#pragma unroll
            for (int c = 0; c < 4; c++) acc[a][b][c] = 0.0f;

    int wm = (wid & 1) * 32, wn = (wid >> 1) * 32;
    const int NCH = HH / KC;   // 128

#pragma unroll
    for (int s = 0; s < STAGES - 1; s++) {
        fill_tiles2(sb + OFF_TILE + s * BUF_SZ2, tid, g_hf, HH, hrows, W, DD, n0, s * KC);
        CP_COMMIT();
    }
    int stage = 0;
    for (int c = 0; c < NCH; c++) {
        if (c + 1 < NCH) CP_WAIT1(); else CP_WAIT0();
        __syncthreads();
        if (c + STAGES - 1 < NCH) {
            int fs = stage + STAGES - 1; if (fs >= STAGES) fs -= STAGES;
            fill_tiles2(sb + OFF_TILE + fs * BUF_SZ2, tid, g_hf, HH, hrows, W, DD, n0,
                        (c + STAGES - 1) * KC);
            CP_COMMIT();
        }
        compute_chunk2(sb + OFF_TILE + stage * BUF_SZ2, lane, wm, wn, acc);
        stage++; if (stage >= STAGES) stage = 0;
    }

    const float* bb = b2 + (size_t)e * DD + n0;
#pragma unroll
    for (int mt = 0; mt < 2; mt++) {
#pragma unroll
        for (int nt = 0; nt < 4; nt++) {
            int col = wn + nt * 8 + (lane & 3) * 2;
            float bv0 = bb[col], bv1 = bb[col + 1];
#pragma unroll
            for (int half = 0; half < 2; half++) {
                int li = wm + mt * 16 + (lane >> 2) + half * 8;
                int hr = hrows[li];
                if (hr < 0) continue;
                float g = gws[li];
                float2 o;
                o.x = g * (acc[mt][nt][half * 2 + 0] + bv0);
                o.y = g * (acc[mt][nt][half * 2 + 1] + bv1);
                *(float2*)(g_y + (size_t)hr * DD + n0 + col) = o;
            }
        }
    }
}

// ---------------- combine: out[t] = y[2t] + y[2t+1] ----------------
__global__ void k_combine(float* __restrict__ out) {
    int i = blockIdx.x * blockDim.x + threadIdx.x;
    if (i >= NT * DD / 4) return;
    int t  = i >> 8;
    int d4 = i & 255;
    const float4* y4 = (const float4*)g_y;
    float4 a = y4[(size_t)(2 * t) * 256 + d4];
    float4 b = y4[(size_t)(2 * t + 1) * 256 + d4];
    float4 o; o.x = a.x + b.x; o.y = a.y + b.y; o.z = a.z + b.z; o.w = a.w + b.w;
    ((float4*)out)[i] = o;
}

// ---------------- launch ----------------
extern "C" void kernel_launch(void* const* d_in, const int* in_sizes, int n_in,
                              void* d_out, int out_size) {
    const float* x  = (const float*)d_in[0];
    const float* gw = (const float*)d_in[1];
    const float* gb = (const float*)d_in[2];
    const float* w1 = (const float*)d_in[3];
    const float* b1 = (const float*)d_in[4];
    const float* w2 = (const float*)d_in[5];
    const float* b2 = (const float*)d_in[6];
    float* out = (float*)d_out;

    cudaFuncSetAttribute(k_fc1, cudaFuncAttributeMaxDynamicSharedMemorySize, SMEM_SZ);
    cudaFuncSetAttribute(k_fc2, cudaFuncAttributeMaxDynamicSharedMemorySize, SMEM_SZ2);

    void* cntp;
    cudaGetSymbolAddress(&cntp, g_cnt);
    cudaMemsetAsync(cntp, 0, NE * sizeof(int));

    k_prepass<<<NB_TOTAL, 256>>>(x, gw, gb, w1, w2);

    dim3 g1(HH / BN, NT / BM, NE);    // 32 x 32 x 8
    k_fc1<<<g1, 256, SMEM_SZ>>>(b1);

    dim3 g2(DD / BN, NT / BM2, NE);   // 8 x 64 x 8
    k_fc2<<<g2, 256, SMEM_SZ2>>>(b2);

    k_combine<<<(NT * DD / 4 + 255) / 256, 256>>>(out);
}

// round 13
// speedup vs baseline: 1.1325x; 1.1125x over previous
#include <cuda_runtime.h>
#include <cuda_fp16.h>
#include <math.h>
#include <stdint.h>

// Problem constants
#define NT   4096   // B*T tokens
#define DD   1024   // model dim
#define HH   4096   // hidden dim
#define NE   8      // experts
#define TOPK 2

#define BM 128
#define BN 128
#define KC 32
#define STAGES 4

// ---------------- scratch (static device, no allocation) ----------------
__device__ int   g_cnt[NE];
__device__ int   g_tok [NE * NT];
__device__ float g_gw  [NE * NT];
__device__ int   g_hrow[NE * NT];

__device__ __half g_xf[(size_t)NT * DD];
__device__ __half g_w1f[(size_t)NE * DD * HH];
__device__ __half g_w2f[(size_t)NE * HH * DD];
__device__ __half g_hf[(size_t)NT * TOPK * HH];
__device__ float  g_y[(size_t)NT * TOPK * DD];

// ---------------- PTX helpers (plain sm_103-safe) ----------------
__device__ __forceinline__ uint32_t smem_u32(const void* p) {
    uint32_t a;
    asm("{ .reg .u64 t; cvta.to.shared.u64 t, %1; cvt.u32.u64 %0, t; }" : "=r"(a) : "l"(p));
    return a;
}
__device__ __forceinline__ void cp16(uint32_t dst, const void* src, uint32_t srcsize) {
    asm volatile("cp.async.cg.shared.global [%0], [%1], 16, %2;"
                 :: "r"(dst), "l"(src), "r"(srcsize) : "memory");
}
#define CP_COMMIT()  asm volatile("cp.async.commit_group;" ::: "memory")
#define CP_WAIT1()   asm volatile("cp.async.wait_group 1;" ::: "memory")
#define CP_WAIT0()   asm volatile("cp.async.wait_group 0;" ::: "memory")

__device__ __forceinline__ void ldsm4(uint32_t* r, uint32_t addr) {
    asm volatile("ldmatrix.sync.aligned.m8n8.x4.shared.b16 {%0,%1,%2,%3}, [%4];"
                 : "=r"(r[0]), "=r"(r[1]), "=r"(r[2]), "=r"(r[3]) : "r"(addr));
}
__device__ __forceinline__ void ldsm4t(uint32_t* r, uint32_t addr) {
    asm volatile("ldmatrix.sync.aligned.m8n8.x4.trans.shared.b16 {%0,%1,%2,%3}, [%4];"
                 : "=r"(r[0]), "=r"(r[1]), "=r"(r[2]), "=r"(r[3]) : "r"(addr));
}
__device__ __forceinline__ void mma16816(float* d, const uint32_t* a, uint32_t b0, uint32_t b1) {
    asm volatile("mma.sync.aligned.m16n8k16.row.col.f32.f16.f16.f32 "
                 "{%0,%1,%2,%3}, {%4,%5,%6,%7}, {%8,%9}, {%0,%1,%2,%3};"
                 : "+f"(d[0]), "+f"(d[1]), "+f"(d[2]), "+f"(d[3])
                 : "r"(a[0]), "r"(a[1]), "r"(a[2]), "r"(a[3]), "r"(b0), "r"(b1));
}

// ---------------- SMEM layout ----------------
// A: 128 rows x 32 fp16 (64B) + 16B pad = 80B stride  -> 10240 B
// B: 32 k-rows x 128 fp16 (256B) + 16B pad = 272B stride -> 8704 B
#define AST 80
#define BST 272
#define OFF_TOK  0
#define OFF_HR   512
#define OFF_GWS  1024
#define OFF_TILE 1536
#define A_OFF 0
#define B_OFF 10240
#define BUF_SZ 18944
#define SMEM_SZ (OFF_TILE + STAGES * BUF_SZ)   // 77312

// ---------------- fused prepass: gate + 3 fp32->fp16 conversions ----------------
#define NB_GATE  (NT / 8)                   // 512 blocks, 8 warps each
#define NB_CX    (NT * DD / 4 / 256)        // 4096
#define NB_CW    (NE * DD * HH / 4 / 256)   // 32768
#define NB_TOTAL (NB_GATE + NB_CX + 2 * NB_CW)

__device__ __forceinline__ void conv4(const float* __restrict__ src,
                                      __half* __restrict__ dst, int i) {
    float4 v = ((const float4*)src)[i];
    __half2 a = __floats2half2_rn(v.x, v.y);
    __half2 b = __floats2half2_rn(v.z, v.w);
    ((uint2*)dst)[i] = make_uint2(*(uint32_t*)&a, *(uint32_t*)&b);
}

__global__ void k_prepass(const float* __restrict__ x,
                          const float* __restrict__ gw,
                          const float* __restrict__ gb,
                          const float* __restrict__ w1,
                          const float* __restrict__ w2) {
    int b = blockIdx.x;
    int tid = threadIdx.x;
    if (b < NB_GATE) {
        // ---- gating: one warp per token ----
        int lane = tid & 31;
        int tok = b * 8 + (tid >> 5);
        const float* xr = x + (size_t)tok * DD;
        float acc[NE];
#pragma unroll
        for (int e = 0; e < NE; e++) acc[e] = 0.0f;
        for (int d = lane; d < DD; d += 32) {
            float xv = xr[d];
#pragma unroll
            for (int e = 0; e < NE; e++) acc[e] += xv * gw[d * NE + e];
        }
#pragma unroll
        for (int e = 0; e < NE; e++) {
#pragma unroll
            for (int o = 16; o > 0; o >>= 1)
                acc[e] += __shfl_xor_sync(0xffffffffu, acc[e], o);
        }
        if (lane == 0) {
            float z[NE]; float m = -1e30f;
#pragma unroll
            for (int e = 0; e < NE; e++) { z[e] = acc[e] + gb[e]; m = fmaxf(m, z[e]); }
            float s = 0.0f;
#pragma unroll
            for (int e = 0; e < NE; e++) { z[e] = expf(z[e] - m); s += z[e]; }
            int i1 = 0;
#pragma unroll
            for (int e = 1; e < NE; e++) if (z[e] > z[i1]) i1 = e;
            int i2 = (i1 == 0) ? 1 : 0;
#pragma unroll
            for (int e = 0; e < NE; e++) if (e != i1 && z[e] > z[i2]) i2 = e;
            float inv = 1.0f / s;
            int es[2] = { i1, i2 };
#pragma unroll
            for (int k = 0; k < TOPK; k++) {
                int e = es[k];
                int slot = atomicAdd(&g_cnt[e], 1);
                g_tok [e * NT + slot] = tok;
                g_gw  [e * NT + slot] = z[e] * inv;
                g_hrow[e * NT + slot] = tok * TOPK + k;
            }
        }
    } else if (b < NB_GATE + NB_CX) {
        conv4(x, g_xf, (b - NB_GATE) * 256 + tid);
    } else if (b < NB_GATE + NB_CX + NB_CW) {
        conv4(w1, g_w1f, (b - NB_GATE - NB_CX) * 256 + tid);
    } else {
        conv4(w2, g_w2f, (b - NB_GATE - NB_CX - NB_CW) * 256 + tid);
    }
}

// ---------------- tile fill (cp.async) ----------------
__device__ __forceinline__ void fill_tiles(uint32_t tb, int tid,
                                           const __half* __restrict__ A, int a_ld,
                                           const int* rows,
                                           const __half* __restrict__ B, int b_ld,
                                           int n0, int k0) {
    // A: 128 rows x 32 fp16 = 4 x 16B chunks/row -> 512 chunks
#pragma unroll
    for (int i = 0; i < 2; i++) {
        int id = tid + i * 256;
        int r = id >> 2, c = id & 3;
        int t = rows[r];
        size_t off = (size_t)(t < 0 ? 0 : t) * a_ld + k0 + c * 8;
        cp16(tb + A_OFF + r * AST + c * 16, A + off, (t < 0) ? 0u : 16u);
    }
    // B: 32 k-rows x 128 fp16 = 16 x 16B chunks/row -> 512 chunks
#pragma unroll
    for (int i = 0; i < 2; i++) {
        int id = tid + i * 256;
        int r = id >> 4, c = id & 15;
        size_t off = (size_t)(k0 + r) * b_ld + n0 + c * 8;
        cp16(tb + B_OFF + r * BST + c * 16, B + off, 16u);
    }
}

// ---------------- mma mainloop for one 32-K chunk ----------------
// warp tile: 64 (m) x 32 (n); acc[4 m-tiles][4 n8-tiles][4]
__device__ __forceinline__ void compute_chunk(uint32_t tb, int lane, int wm, int wn,
                                              float acc[4][4][4]) {
    int t  = lane >> 3;
    int lr = lane & 7;
#pragma unroll
    for (int k16 = 0; k16 < KC; k16 += 16) {
        uint32_t a[4][4];
#pragma unroll
        for (int mt = 0; mt < 4; mt++) {
            uint32_t addr = tb + A_OFF + (uint32_t)(wm + mt * 16 + (t & 1) * 8 + lr) * AST
                          + (uint32_t)(k16 + (t >> 1) * 8) * 2;
            ldsm4(a[mt], addr);
        }
#pragma unroll
        for (int j = 0; j < 2; j++) {
            uint32_t b[4];
            uint32_t addr = tb + B_OFF + (uint32_t)(k16 + (t & 1) * 8 + lr) * BST
                          + (uint32_t)(wn + j * 16 + (t >> 1) * 8) * 2;
            ldsm4t(b, addr);
#pragma unroll
            for (int mt = 0; mt < 4; mt++) {
                mma16816(acc[mt][j * 2 + 0], a[mt], b[0], b[1]);
                mma16816(acc[mt][j * 2 + 1], a[mt], b[2], b[3]);
            }
        }
    }
}

// pipelined mainloop shared by both FC kernels (NCH > STAGES-1)
__device__ __forceinline__ void gemm_mainloop(uint32_t sb, int tid, int lane, int wm, int wn,
                                              const __half* __restrict__ A, int a_ld,
                                              const int* rows,
                                              const __half* __restrict__ B, int b_ld,
                                              int n0, int NCH, float acc[4][4][4]) {
#pragma unroll
    for (int s = 0; s < STAGES - 1; s++) {
        fill_tiles(sb + OFF_TILE + s * BUF_SZ, tid, A, a_ld, rows, B, b_ld, n0, s * KC);
        CP_COMMIT();
    }
    int stage = 0;
    for (int c = 0; c < NCH; c++) {
        if (c + 1 < NCH) CP_WAIT1(); else CP_WAIT0();
        __syncthreads();
        if (c + STAGES - 1 < NCH) {
            int fs = stage + STAGES - 1; if (fs >= STAGES) fs -= STAGES;
            fill_tiles(sb + OFF_TILE + fs * BUF_SZ, tid, A, a_ld, rows, B, b_ld, n0,
                       (c + STAGES - 1) * KC);
            CP_COMMIT();
        }
        compute_chunk(sb + OFF_TILE + stage * BUF_SZ, lane, wm, wn, acc);
        stage++; if (stage >= STAGES) stage = 0;
    }
}

// ---------------- FC1: h[hrow] = relu(x[tok] @ w1[e] + b1[e]) -> fp16 ----------------
__global__ void __launch_bounds__(256, 2)
k_fc1(const float* __restrict__ b1) {
    int e = blockIdx.z;
    int cnt = g_cnt[e];
    int m0 = blockIdx.y * BM;
    if (m0 >= cnt) return;
    int n0 = blockIdx.x * BN;

    extern __shared__ char smem[];
    uint32_t sb = smem_u32(smem);
    int tid = threadIdx.x, wid = tid >> 5, lane = tid & 31;
    int* toks  = (int*)(smem + OFF_TOK);
    int* hrows = (int*)(smem + OFF_HR);
    if (tid < BM) {
        int s = m0 + tid;
        toks [tid] = (s < cnt) ? g_tok [e * NT + s] : -1;
        hrows[tid] = (s < cnt) ? g_hrow[e * NT + s] : -1;
    }
    __syncthreads();

    const __half* W = g_w1f + (size_t)e * DD * HH;

    float acc[4][4][4];
#pragma unroll
    for (int a = 0; a < 4; a++)
#pragma unroll
        for (int b = 0; b < 4; b++)
#pragma unroll
            for (int c = 0; c < 4; c++) acc[a][b][c] = 0.0f;

    int wm = (wid >> 2) * 64, wn = (wid & 3) * 32;

    gemm_mainloop(sb, tid, lane, wm, wn, g_xf, DD, toks, W, HH, n0, DD / KC, acc);

    // epilogue: bias + relu -> fp16 h
    const float* bb = b1 + (size_t)e * HH + n0;
#pragma unroll
    for (int mt = 0; mt < 4; mt++) {
#pragma unroll
        for (int nt = 0; nt < 4; nt++) {
            int col = wn + nt * 8 + (lane & 3) * 2;
            float bv0 = bb[col], bv1 = bb[col + 1];
#pragma unroll
            for (int half = 0; half < 2; half++) {
                int li = wm + mt * 16 + (lane >> 2) + half * 8;
                int hr = hrows[li];
                if (hr < 0) continue;
                float h0 = fmaxf(acc[mt][nt][half * 2 + 0] + bv0, 0.0f);
                float h1 = fmaxf(acc[mt][nt][half * 2 + 1] + bv1, 0.0f);
                __half2 hp = __floats2half2_rn(h0, h1);
                *(uint32_t*)(g_hf + (size_t)hr * HH + n0 + col) = *(uint32_t*)&hp;
            }
        }
    }
}

// ---------------- FC2: y[hrow] = gate * (h[hrow] @ w2[e] + b2[e]) ----------------
__global__ void __launch_bounds__(256, 2)
k_fc2(const float* __restrict__ b2) {
    int e = blockIdx.z;
    int cnt = g_cnt[e];
    int m0 = blockIdx.y * BM;
    if (m0 >= cnt) return;
    int n0 = blockIdx.x * BN;

    extern __shared__ char smem[];
    uint32_t sb = smem_u32(smem);
    int tid = threadIdx.x, wid = tid >> 5, lane = tid & 31;
    int*   hrows = (int*)(smem + OFF_HR);
    float* gws   = (float*)(smem + OFF_GWS);
    if (tid < BM) {
        int s = m0 + tid;
        hrows[tid] = (s < cnt) ? g_hrow[e * NT + s] : -1;
        gws  [tid] = (s < cnt) ? g_gw  [e * NT + s] : 0.0f;
    }
    __syncthreads();

    const __half* W = g_w2f + (size_t)e * HH * DD;

    float acc[4][4][4];
#pragma unroll
    for (int a = 0; a < 4; a++)
#pragma unroll
        for (int b = 0; b < 4; b++)
#pragma unroll
            for (int c = 0; c < 4; c++) acc[a][b][c] = 0.0f;

    int wm = (wid >> 2) * 64, wn = (wid & 3) * 32;

    gemm_mainloop(sb, tid, lane, wm, wn, g_hf, HH, hrows, W, DD, n0, HH / KC, acc);

    const float* bb = b2 + (size_t)e * DD + n0;
#pragma unroll
    for (int mt = 0; mt < 4; mt++) {
#pragma unroll
        for (int nt = 0; nt < 4; nt++) {
            int col = wn + nt * 8 + (lane & 3) * 2;
            float bv0 = bb[col], bv1 = bb[col + 1];
#pragma unroll
            for (int half = 0; half < 2; half++) {
                int li = wm + mt * 16 + (lane >> 2) + half * 8;
                int hr = hrows[li];
                if (hr < 0) continue;
                float g = gws[li];
                float2 o;
                o.x = g * (acc[mt][nt][half * 2 + 0] + bv0);
                o.y = g * (acc[mt][nt][half * 2 + 1] + bv1);
                *(float2*)(g_y + (size_t)hr * DD + n0 + col) = o;
            }
        }
    }
}

// ---------------- combine: out[t] = y[2t] + y[2t+1] ----------------
__global__ void k_combine(float* __restrict__ out) {
    int i = blockIdx.x * blockDim.x + threadIdx.x;
    if (i >= NT * DD / 4) return;
    int t  = i >> 8;
    int d4 = i & 255;
    const float4* y4 = (const float4*)g_y;
    float4 a = y4[(size_t)(2 * t) * 256 + d4];
    float4 b = y4[(size_t)(2 * t + 1) * 256 + d4];
    float4 o; o.x = a.x + b.x; o.y = a.y + b.y; o.z = a.z + b.z; o.w = a.w + b.w;
    ((float4*)out)[i] = o;
}

// ---------------- launch ----------------
extern "C" void kernel_launch(void* const* d_in, const int* in_sizes, int n_in,
                              void* d_out, int out_size) {
    const float* x  = (const float*)d_in[0];
    const float* gw = (const float*)d_in[1];
    const float* gb = (const float*)d_in[2];
    const float* w1 = (const float*)d_in[3];
    const float* b1 = (const float*)d_in[4];
    const float* w2 = (const float*)d_in[5];
    const float* b2 = (const float*)d_in[6];
    float* out = (float*)d_out;

    cudaFuncSetAttribute(k_fc1, cudaFuncAttributeMaxDynamicSharedMemorySize, SMEM_SZ);
    cudaFuncSetAttribute(k_fc2, cudaFuncAttributeMaxDynamicSharedMemorySize, SMEM_SZ);

    void* cntp;
    cudaGetSymbolAddress(&cntp, g_cnt);
    cudaMemsetAsync(cntp, 0, NE * sizeof(int));

    k_prepass<<<NB_TOTAL, 256>>>(x, gw, gb, w1, w2);

    dim3 g1(HH / BN, NT / BM, NE);   // 32 x 32 x 8
    k_fc1<<<g1, 256, SMEM_SZ>>>(b1);

    dim3 g2(DD / BN, NT / BM, NE);   // 8 x 32 x 8
    k_fc2<<<g2, 256, SMEM_SZ>>>(b2);

    k_combine<<<(NT * DD / 4 + 255) / 256, 256>>>(out);
}